// round 1
// baseline (speedup 1.0000x reference)
#include <cuda_runtime.h>

// ---------------- problem constants ----------------
#define N_NODES 100000
#define N_EDGES 1600000
#define ET      (N_EDGES + N_NODES)   // edges + self-loops
#define F_IN    128

// ---------------- scratch (no allocs allowed) ----------------
__device__ __align__(16) float g_h1  [N_NODES * 64];
__device__ float g_as1 [N_NODES * 8];
__device__ float g_ad1 [N_NODES * 8];
__device__ __align__(16) float g_agg1[N_NODES * 64];
__device__ float g_den1[N_NODES * 8];
__device__ __align__(16) float g_h2  [N_NODES * 64];
__device__ float g_as2 [N_NODES];
__device__ float g_ad2 [N_NODES];
__device__ __align__(16) float g_agg2[N_NODES * 64];
__device__ float g_den2[N_NODES];

// sm_90+ vectorized global reduction: 1 L2 atomic op per 16 bytes
__device__ __forceinline__ void red_add_v4(float* addr, float4 v) {
    asm volatile("red.global.add.v4.f32 [%0], {%1, %2, %3, %4};"
                 :: "l"(addr), "f"(v.x), "f"(v.y), "f"(v.z), "f"(v.w)
                 : "memory");
}

// ---------------- kernel 1: h1 = x@W1, alpha dots, zero agg1/den1 ----------------
// one node per block, 64 threads (one per output channel)
__global__ void k_l1_node(const float* __restrict__ x,
                          const float* __restrict__ W1,
                          const float* __restrict__ as1,
                          const float* __restrict__ ad1) {
    int node = blockIdx.x;
    int c = threadIdx.x;
    __shared__ float sx[F_IN];
    sx[c]      = x[(long long)node * F_IN + c];
    sx[c + 64] = x[(long long)node * F_IN + c + 64];
    __syncthreads();
    float acc = 0.f;
#pragma unroll 16
    for (int k = 0; k < F_IN; k++) acc += sx[k] * W1[k * 64 + c];
    g_h1[node * 64 + c] = acc;
    // a_src1/a_dst1 are [8,8] row-major -> flat index == c
    float vs = acc * as1[c];
    float vd = acc * ad1[c];
    // reduce within each 8-lane head group
#pragma unroll
    for (int off = 1; off < 8; off <<= 1) {
        vs += __shfl_xor_sync(0xffffffffu, vs, off);
        vd += __shfl_xor_sync(0xffffffffu, vd, off);
    }
    if ((c & 7) == 0) {
        g_as1[node * 8 + (c >> 3)] = vs;
        g_ad1[node * 8 + (c >> 3)] = vd;
    }
    g_agg1[node * 64 + c] = 0.f;
    if (c < 8) g_den1[node * 8 + c] = 0.f;
}

// ---------------- kernel 2: layer-1 edge scatter ----------------
// 16 lanes per edge (2 edges per warp). lane l handles channels 4l..4l+3.
__global__ void k_l1_edge(const int* __restrict__ ei) {
    int gw   = (blockIdx.x * blockDim.x + threadIdx.x) >> 5;
    int lane = threadIdx.x & 31;
    int sub  = lane >> 4;
    int l    = lane & 15;
    long long edge = (long long)gw * 2 + sub;
    if (edge >= ET) return;
    int src, dst;
    if (edge < N_EDGES) { src = ei[edge]; dst = ei[N_EDGES + edge]; }
    else                { src = dst = (int)(edge - N_EDGES); }
    int head = l >> 1;                       // 2 chunks of 4 channels per head
    float e = g_as1[src * 8 + head] + g_ad1[dst * 8 + head];
    e = e > 0.f ? e : 0.2f * e;              // leaky relu
    float p = __expf(e);                     // no max-shift needed (shift-invariant)
    if ((l & 1) == 0) atomicAdd(&g_den1[dst * 8 + head], p);
    float4 hv = *reinterpret_cast<const float4*>(&g_h1[src * 64 + 4 * l]);
    red_add_v4(&g_agg1[dst * 64 + 4 * l],
               make_float4(hv.x * p, hv.y * p, hv.z * p, hv.w * p));
}

// ---------------- kernel 3: normalize+bias+ELU, h2 = out1@W2, alpha2, zero agg2 ----------------
__global__ void k_mid_node(const float* __restrict__ b1,
                           const float* __restrict__ W2,
                           const float* __restrict__ as2,
                           const float* __restrict__ ad2) {
    int node = blockIdx.x;
    int c = threadIdx.x;
    __shared__ float so[64];
    __shared__ float sred[4];
    float den = g_den1[node * 8 + (c >> 3)] + 1e-16f;
    float v = g_agg1[node * 64 + c] / den + b1[c];
    v = v > 0.f ? v : expm1f(v);             // ELU (alpha=1)
    so[c] = v;
    __syncthreads();
    float acc = 0.f;
#pragma unroll 16
    for (int k = 0; k < 64; k++) acc += so[k] * W2[k * 64 + c];
    g_h2[node * 64 + c] = acc;
    float vs = acc * as2[c];
    float vd = acc * ad2[c];
#pragma unroll
    for (int off = 1; off < 32; off <<= 1) {
        vs += __shfl_xor_sync(0xffffffffu, vs, off);
        vd += __shfl_xor_sync(0xffffffffu, vd, off);
    }
    int w = c >> 5;
    if ((c & 31) == 0) { sred[w] = vs; sred[2 + w] = vd; }
    __syncthreads();
    if (c == 0) {
        g_as2[node] = sred[0] + sred[1];
        g_ad2[node] = sred[2] + sred[3];
        g_den2[node] = 0.f;
    }
    g_agg2[node * 64 + c] = 0.f;
}

// ---------------- kernel 4: layer-2 edge scatter (single head) ----------------
__global__ void k_l2_edge(const int* __restrict__ ei) {
    int gw   = (blockIdx.x * blockDim.x + threadIdx.x) >> 5;
    int lane = threadIdx.x & 31;
    int sub  = lane >> 4;
    int l    = lane & 15;
    long long edge = (long long)gw * 2 + sub;
    if (edge >= ET) return;
    int src, dst;
    if (edge < N_EDGES) { src = ei[edge]; dst = ei[N_EDGES + edge]; }
    else                { src = dst = (int)(edge - N_EDGES); }
    float e = g_as2[src] + g_ad2[dst];
    e = e > 0.f ? e : 0.2f * e;
    float p = __expf(e);
    if (l == 0) atomicAdd(&g_den2[dst], p);
    float4 hv = *reinterpret_cast<const float4*>(&g_h2[src * 64 + 4 * l]);
    red_add_v4(&g_agg2[dst * 64 + 4 * l],
               make_float4(hv.x * p, hv.y * p, hv.z * p, hv.w * p));
}

// ---------------- kernel 5: normalize + bias + log_softmax ----------------
__global__ void k_out_node(const float* __restrict__ b2, float* __restrict__ out) {
    int node = blockIdx.x;
    int c = threadIdx.x;
    __shared__ float sred[4];
    float den = g_den2[node] + 1e-16f;
    float y = g_agg2[node * 64 + c] / den + b2[c];
    float m = y;
#pragma unroll
    for (int off = 1; off < 32; off <<= 1)
        m = fmaxf(m, __shfl_xor_sync(0xffffffffu, m, off));
    int w = c >> 5;
    if ((c & 31) == 0) sred[w] = m;
    __syncthreads();
    m = fmaxf(sred[0], sred[1]);
    float ex = __expf(y - m);
    float s = ex;
#pragma unroll
    for (int off = 1; off < 32; off <<= 1)
        s += __shfl_xor_sync(0xffffffffu, s, off);
    if ((c & 31) == 0) sred[2 + w] = s;
    __syncthreads();
    s = sred[2] + sred[3];
    out[(long long)node * 64 + c] = y - m - __logf(s);
}

// ---------------- launcher ----------------
extern "C" void kernel_launch(void* const* d_in, const int* in_sizes, int n_in,
                              void* d_out, int out_size) {
    const float* x   = (const float*)d_in[0];
    const int*   ei  = (const int*)  d_in[1];
    const float* W1  = (const float*)d_in[2];
    const float* as1 = (const float*)d_in[3];
    const float* ad1 = (const float*)d_in[4];
    const float* b1  = (const float*)d_in[5];
    const float* W2  = (const float*)d_in[6];
    const float* as2 = (const float*)d_in[7];
    const float* ad2 = (const float*)d_in[8];
    const float* b2  = (const float*)d_in[9];
    float* out = (float*)d_out;

    int eblocks = (ET + 15) / 16;   // 16 edges per 256-thread block

    k_l1_node<<<N_NODES, 64>>>(x, W1, as1, ad1);
    k_l1_edge<<<eblocks, 256>>>(ei);
    k_mid_node<<<N_NODES, 64>>>(b1, W2, as2, ad2);
    k_l2_edge<<<eblocks, 256>>>(ei);
    k_out_node<<<N_NODES, 64>>>(b2, out);
}

// round 2
// speedup vs baseline: 1.2264x; 1.2264x over previous
#include <cuda_runtime.h>

// ---------------- problem constants ----------------
#define N_NODES 100000
#define N_EDGES 1600000
#define ET      (N_EDGES + N_NODES)   // edges + self-loops
#define F_IN    128
#define SCAN_TILE 512
#define NTILES  196                   // ceil(100000/512)

// ---------------- scratch (no allocs allowed) ----------------
__device__ __align__(16) float g_h1  [N_NODES * 64];
__device__ __align__(16) float g_out1[N_NODES * 64];
__device__ __align__(16) float g_h2  [N_NODES * 64];
__device__ float g_as1 [N_NODES * 8];
__device__ float g_ad1 [N_NODES * 8];
__device__ float g_as2 [N_NODES];
__device__ float g_ad2 [N_NODES];
__device__ int   g_deg [N_NODES];
__device__ int   g_off [N_NODES + 1];
__device__ int   g_cur [N_NODES];
__device__ int   g_tsum[NTILES];
__device__ int   g_toff[NTILES];
__device__ int   g_csr [ET];

// ================= CSR build =================
__global__ void k_zero_deg() {
    int i = blockIdx.x * 256 + threadIdx.x;
    if (i < N_NODES) g_deg[i] = 0;
}

__global__ void k_hist(const int* __restrict__ ei) {
    int e = blockIdx.x * 256 + threadIdx.x;
    if (e >= ET) return;
    int dst = (e < N_EDGES) ? ei[N_EDGES + e] : (e - N_EDGES);
    atomicAdd(&g_deg[dst], 1);
}

__global__ void k_sums() {
    __shared__ int s[SCAN_TILE];
    int t = threadIdx.x;
    int i = blockIdx.x * SCAN_TILE + t;
    s[t] = (i < N_NODES) ? g_deg[i] : 0;
    __syncthreads();
    for (int st = SCAN_TILE / 2; st > 0; st >>= 1) {
        if (t < st) s[t] += s[t + st];
        __syncthreads();
    }
    if (t == 0) g_tsum[blockIdx.x] = s[0];
}

__global__ void k_top() {
    __shared__ int sv[256];
    int t = threadIdx.x;
    sv[t] = (t < NTILES) ? g_tsum[t] : 0;
    __syncthreads();
    if (t == 0) {
        int r = 0;
        for (int b = 0; b < NTILES; b++) { int v = sv[b]; sv[b] = r; r += v; }
    }
    __syncthreads();
    if (t < NTILES) g_toff[t] = sv[t];
}

__global__ void k_fin() {
    __shared__ int s[SCAN_TILE];
    int t = threadIdx.x;
    int i = blockIdx.x * SCAN_TILE + t;
    int v = (i < N_NODES) ? g_deg[i] : 0;
    s[t] = v;
    __syncthreads();
    for (int off = 1; off < SCAN_TILE; off <<= 1) {
        int u = (t >= off) ? s[t - off] : 0;
        __syncthreads();
        s[t] += u;
        __syncthreads();
    }
    int excl = s[t] - v + g_toff[blockIdx.x];
    if (i < N_NODES) { g_off[i] = excl; g_cur[i] = excl; }
    if (i == 0) g_off[N_NODES] = ET;
}

__global__ void k_scatter(const int* __restrict__ ei) {
    int e = blockIdx.x * 256 + threadIdx.x;
    if (e >= ET) return;
    int src, dst;
    if (e < N_EDGES) { src = ei[e]; dst = ei[N_EDGES + e]; }
    else             { src = dst = e - N_EDGES; }
    int pos = atomicAdd(&g_cur[dst], 1);
    g_csr[pos] = src;
}

// ================= GEMM 1: h1 = x @ W1, per-head alpha dots =================
// 256 threads, 32 nodes/block (3125 blocks). Thread: 2 nodes x 4 channels.
#define FMA4(acc, xv, wv) \
    acc.x = fmaf((xv), (wv).x, acc.x); acc.y = fmaf((xv), (wv).y, acc.y); \
    acc.z = fmaf((xv), (wv).z, acc.z); acc.w = fmaf((xv), (wv).w, acc.w);

__global__ __launch_bounds__(256) void k_gemm1(
        const float* __restrict__ x, const float* __restrict__ W1,
        const float* __restrict__ a_s, const float* __restrict__ a_d) {
    __shared__ float sW[64 * 64];          // one k-chunk of W1
    __shared__ float sX[32 * 132];         // 32 nodes, stride 132
    __shared__ float sas[64], sad[64];
    __shared__ float sAS[32 * 8], sAD[32 * 8];
    int t = threadIdx.x;
    int node0 = blockIdx.x * 32;
    if (t < 64) { sas[t] = a_s[t]; sad[t] = a_d[t]; }
    sAS[t] = 0.f; sAD[t] = 0.f;
#pragma unroll
    for (int i = 0; i < 16; i++) {
        int idx = t + 256 * i;             // 0..4095
        int n = idx >> 7, k = idx & 127;
        sX[n * 132 + k] = x[(long long)(node0 + n) * F_IN + k];
    }
    int ng = t >> 4, cg = t & 15;
    int nA = ng * 2, nB = nA + 1;
    int c0 = cg * 4;
    float4 a0 = make_float4(0.f, 0.f, 0.f, 0.f);
    float4 a1 = make_float4(0.f, 0.f, 0.f, 0.f);

    for (int kc = 0; kc < 128; kc += 64) {
        __syncthreads();
#pragma unroll
        for (int i = 0; i < 16; i++) {
            int idx = t + 256 * i;         // 0..4095 -> [k][c]
            int k = idx >> 6, c = idx & 63;
            sW[idx] = W1[(kc + k) * 64 + c];
        }
        __syncthreads();
#pragma unroll
        for (int k4 = 0; k4 < 64; k4 += 4) {
            float4 xa = *(const float4*)&sX[nA * 132 + kc + k4];
            float4 xb = *(const float4*)&sX[nB * 132 + kc + k4];
            float4 w0 = *(const float4*)&sW[(k4 + 0) * 64 + c0];
            float4 w1 = *(const float4*)&sW[(k4 + 1) * 64 + c0];
            float4 w2 = *(const float4*)&sW[(k4 + 2) * 64 + c0];
            float4 w3 = *(const float4*)&sW[(k4 + 3) * 64 + c0];
            FMA4(a0, xa.x, w0); FMA4(a0, xa.y, w1); FMA4(a0, xa.z, w2); FMA4(a0, xa.w, w3);
            FMA4(a1, xb.x, w0); FMA4(a1, xb.y, w1); FMA4(a1, xb.z, w2); FMA4(a1, xb.w, w3);
        }
    }
    // write h1 + alpha partials (head = 8 channels -> cg>>1)
    int head = cg >> 1;
    *(float4*)&g_h1[(long long)(node0 + nA) * 64 + c0] = a0;
    *(float4*)&g_h1[(long long)(node0 + nB) * 64 + c0] = a1;
    float psA = a0.x * sas[c0] + a0.y * sas[c0 + 1] + a0.z * sas[c0 + 2] + a0.w * sas[c0 + 3];
    float pdA = a0.x * sad[c0] + a0.y * sad[c0 + 1] + a0.z * sad[c0 + 2] + a0.w * sad[c0 + 3];
    float psB = a1.x * sas[c0] + a1.y * sas[c0 + 1] + a1.z * sas[c0 + 2] + a1.w * sas[c0 + 3];
    float pdB = a1.x * sad[c0] + a1.y * sad[c0 + 1] + a1.z * sad[c0 + 2] + a1.w * sad[c0 + 3];
    atomicAdd(&sAS[nA * 8 + head], psA); atomicAdd(&sAD[nA * 8 + head], pdA);
    atomicAdd(&sAS[nB * 8 + head], psB); atomicAdd(&sAD[nB * 8 + head], pdB);
    __syncthreads();
    g_as1[node0 * 8 + t] = sAS[t];         // 256 entries = 32 nodes x 8 heads
    g_ad1[node0 * 8 + t] = sAD[t];
}

// ================= agg layer 1 (warp per node) + normalize + bias + ELU =================
__global__ __launch_bounds__(256) void k_agg1(const float* __restrict__ b1) {
    int warp = threadIdx.x >> 5, lane = threadIdx.x & 31;
    int node = blockIdx.x * 8 + warp;
    int head = lane >> 2;                  // 2 channels/lane, 8 ch/head
    float adv = g_ad1[node * 8 + head];
    int beg = g_off[node], end = g_off[node + 1];
    float ax = 0.f, ay = 0.f, den = 0.f;
#pragma unroll 4
    for (int e = beg; e < end; e++) {
        int s = g_csr[e];
        float asv = g_as1[s * 8 + head];
        float ev = asv + adv;
        ev = ev > 0.f ? ev : 0.2f * ev;
        float p = __expf(ev);
        float2 h = *(const float2*)&g_h1[(long long)s * 64 + lane * 2];
        ax = fmaf(p, h.x, ax); ay = fmaf(p, h.y, ay); den += p;
    }
    float inv = 1.f / (den + 1e-16f);
    float2 bb = *(const float2*)&b1[lane * 2];
    float vx = ax * inv + bb.x;
    float vy = ay * inv + bb.y;
    vx = vx > 0.f ? vx : expm1f(vx);       // ELU
    vy = vy > 0.f ? vy : expm1f(vy);
    *(float2*)&g_out1[(long long)node * 64 + lane * 2] = make_float2(vx, vy);
}

// ================= GEMM 2: h2 = out1 @ W2, alpha2 dots =================
__global__ __launch_bounds__(256) void k_gemm2(
        const float* __restrict__ W2,
        const float* __restrict__ a_s, const float* __restrict__ a_d) {
    __shared__ float sW[64 * 64];
    __shared__ float sX[32 * 68];
    __shared__ float sas[64], sad[64];
    __shared__ float sAS[32], sAD[32];
    int t = threadIdx.x;
    int node0 = blockIdx.x * 32;
    if (t < 64) { sas[t] = a_s[t]; sad[t] = a_d[t]; }
    if (t < 32) { sAS[t] = 0.f; sAD[t] = 0.f; }
#pragma unroll
    for (int i = 0; i < 8; i++) {
        int idx = t + 256 * i;             // 0..2047
        int n = idx >> 6, k = idx & 63;
        sX[n * 68 + k] = g_out1[(long long)(node0 + n) * 64 + k];
    }
#pragma unroll
    for (int i = 0; i < 16; i++) {
        int idx = t + 256 * i;
        sW[idx] = W2[idx];
    }
    __syncthreads();
    int ng = t >> 4, cg = t & 15;
    int nA = ng * 2, nB = nA + 1;
    int c0 = cg * 4;
    float4 a0 = make_float4(0.f, 0.f, 0.f, 0.f);
    float4 a1 = make_float4(0.f, 0.f, 0.f, 0.f);
#pragma unroll
    for (int k4 = 0; k4 < 64; k4 += 4) {
        float4 xa = *(const float4*)&sX[nA * 68 + k4];
        float4 xb = *(const float4*)&sX[nB * 68 + k4];
        float4 w0 = *(const float4*)&sW[(k4 + 0) * 64 + c0];
        float4 w1 = *(const float4*)&sW[(k4 + 1) * 64 + c0];
        float4 w2 = *(const float4*)&sW[(k4 + 2) * 64 + c0];
        float4 w3 = *(const float4*)&sW[(k4 + 3) * 64 + c0];
        FMA4(a0, xa.x, w0); FMA4(a0, xa.y, w1); FMA4(a0, xa.z, w2); FMA4(a0, xa.w, w3);
        FMA4(a1, xb.x, w0); FMA4(a1, xb.y, w1); FMA4(a1, xb.z, w2); FMA4(a1, xb.w, w3);
    }
    *(float4*)&g_h2[(long long)(node0 + nA) * 64 + c0] = a0;
    *(float4*)&g_h2[(long long)(node0 + nB) * 64 + c0] = a1;
    float psA = a0.x * sas[c0] + a0.y * sas[c0 + 1] + a0.z * sas[c0 + 2] + a0.w * sas[c0 + 3];
    float pdA = a0.x * sad[c0] + a0.y * sad[c0 + 1] + a0.z * sad[c0 + 2] + a0.w * sad[c0 + 3];
    float psB = a1.x * sas[c0] + a1.y * sas[c0 + 1] + a1.z * sas[c0 + 2] + a1.w * sas[c0 + 3];
    float pdB = a1.x * sad[c0] + a1.y * sad[c0 + 1] + a1.z * sad[c0 + 2] + a1.w * sad[c0 + 3];
    atomicAdd(&sAS[nA], psA); atomicAdd(&sAD[nA], pdA);
    atomicAdd(&sAS[nB], psB); atomicAdd(&sAD[nB], pdB);
    __syncthreads();
    if (t < 32) { g_as2[node0 + t] = sAS[t]; g_ad2[node0 + t] = sAD[t]; }
}

// ================= agg layer 2 + bias + log_softmax =================
__global__ __launch_bounds__(256) void k_agg2(const float* __restrict__ b2,
                                              float* __restrict__ out) {
    int warp = threadIdx.x >> 5, lane = threadIdx.x & 31;
    int node = blockIdx.x * 8 + warp;
    float adv = g_ad2[node];
    int beg = g_off[node], end = g_off[node + 1];
    float ax = 0.f, ay = 0.f, den = 0.f;
#pragma unroll 4
    for (int e = beg; e < end; e++) {
        int s = g_csr[e];
        float asv = g_as2[s];
        float ev = asv + adv;
        ev = ev > 0.f ? ev : 0.2f * ev;
        float p = __expf(ev);
        float2 h = *(const float2*)&g_h2[(long long)s * 64 + lane * 2];
        ax = fmaf(p, h.x, ax); ay = fmaf(p, h.y, ay); den += p;
    }
    float inv = 1.f / (den + 1e-16f);
    float2 bb = *(const float2*)&b2[lane * 2];
    float yx = ax * inv + bb.x;
    float yy = ay * inv + bb.y;
    // log_softmax over 64 channels (warp reduce)
    float m = fmaxf(yx, yy);
#pragma unroll
    for (int off = 16; off > 0; off >>= 1)
        m = fmaxf(m, __shfl_xor_sync(0xffffffffu, m, off));
    float es = __expf(yx - m) + __expf(yy - m);
#pragma unroll
    for (int off = 16; off > 0; off >>= 1)
        es += __shfl_xor_sync(0xffffffffu, es, off);
    float ls = __logf(es);
    *(float2*)&out[(long long)node * 64 + lane * 2] = make_float2(yx - m - ls, yy - m - ls);
}

// ---------------- launcher ----------------
extern "C" void kernel_launch(void* const* d_in, const int* in_sizes, int n_in,
                              void* d_out, int out_size) {
    const float* x   = (const float*)d_in[0];
    const int*   ei  = (const int*)  d_in[1];
    const float* W1  = (const float*)d_in[2];
    const float* as1 = (const float*)d_in[3];
    const float* ad1 = (const float*)d_in[4];
    const float* b1  = (const float*)d_in[5];
    const float* W2  = (const float*)d_in[6];
    const float* as2 = (const float*)d_in[7];
    const float* ad2 = (const float*)d_in[8];
    const float* b2  = (const float*)d_in[9];
    float* out = (float*)d_out;

    int eblocks = (ET + 255) / 256;        // 6641

    // CSR build (edge structure shared by both layers)
    k_zero_deg<<<(N_NODES + 255) / 256, 256>>>();
    k_hist<<<eblocks, 256>>>(ei);
    k_sums<<<NTILES, SCAN_TILE>>>();
    k_top<<<1, 256>>>();
    k_fin<<<NTILES, SCAN_TILE>>>();
    k_scatter<<<eblocks, 256>>>(ei);

    // layer 1
    k_gemm1<<<N_NODES / 32, 256>>>(x, W1, as1, ad1);
    k_agg1<<<N_NODES / 8, 256>>>(b1);
    // layer 2
    k_gemm2<<<N_NODES / 32, 256>>>(W2, as2, ad2);
    k_agg2<<<N_NODES / 8, 256>>>(b2, out);
}

// round 3
// speedup vs baseline: 1.9052x; 1.5535x over previous
#include <cuda_runtime.h>

// ---------------- problem constants ----------------
#define N_NODES 100000
#define N_EDGES 1600000
#define ET      (N_EDGES + N_NODES)   // edges + self-loops
#define F_IN    128
#define SCAN_TILE 512
#define NTILES  196                   // ceil(100000/512)
#define FULLMASK 0xffffffffu

// ---------------- scratch (no allocs allowed) ----------------
__device__ __align__(16) float g_h1  [N_NODES * 64];
__device__ __align__(16) float g_out1[N_NODES * 64];
__device__ __align__(16) float g_h2  [N_NODES * 64];
__device__ float g_as1 [N_NODES * 8];
__device__ float g_ad1 [N_NODES * 8];
__device__ float g_as2 [N_NODES];
__device__ float g_ad2 [N_NODES];
__device__ int   g_deg [N_NODES];
__device__ int   g_off [N_NODES + 1];
__device__ int   g_cur [N_NODES];
__device__ int   g_tsum[NTILES];
__device__ int   g_toff[NTILES];
__device__ int   g_csr [ET];

// ================= CSR build =================
__global__ void k_zero_deg() {
    int i = blockIdx.x * 256 + threadIdx.x;
    if (i < N_NODES) g_deg[i] = 0;
}

__global__ void k_hist(const int* __restrict__ ei) {
    int e = blockIdx.x * 256 + threadIdx.x;
    if (e >= ET) return;
    int dst = (e < N_EDGES) ? ei[N_EDGES + e] : (e - N_EDGES);
    atomicAdd(&g_deg[dst], 1);
}

__global__ void k_sums() {
    __shared__ int s[SCAN_TILE];
    int t = threadIdx.x;
    int i = blockIdx.x * SCAN_TILE + t;
    s[t] = (i < N_NODES) ? g_deg[i] : 0;
    __syncthreads();
    for (int st = SCAN_TILE / 2; st > 0; st >>= 1) {
        if (t < st) s[t] += s[t + st];
        __syncthreads();
    }
    if (t == 0) g_tsum[blockIdx.x] = s[0];
}

// parallel exclusive scan of the 196 tile sums
__global__ void k_top() {
    __shared__ int s[256];
    int t = threadIdx.x;
    int v = (t < NTILES) ? g_tsum[t] : 0;
    s[t] = v;
    __syncthreads();
    for (int off = 1; off < 256; off <<= 1) {
        int u = (t >= off) ? s[t - off] : 0;
        __syncthreads();
        s[t] += u;
        __syncthreads();
    }
    if (t < NTILES) g_toff[t] = s[t] - v;
}

__global__ void k_fin() {
    __shared__ int s[SCAN_TILE];
    int t = threadIdx.x;
    int i = blockIdx.x * SCAN_TILE + t;
    int v = (i < N_NODES) ? g_deg[i] : 0;
    s[t] = v;
    __syncthreads();
    for (int off = 1; off < SCAN_TILE; off <<= 1) {
        int u = (t >= off) ? s[t - off] : 0;
        __syncthreads();
        s[t] += u;
        __syncthreads();
    }
    int excl = s[t] - v + g_toff[blockIdx.x];
    if (i < N_NODES) { g_off[i] = excl; g_cur[i] = excl; }
    if (i == 0) g_off[N_NODES] = ET;
}

__global__ void k_scatter(const int* __restrict__ ei) {
    int e = blockIdx.x * 256 + threadIdx.x;
    if (e >= ET) return;
    int src, dst;
    if (e < N_EDGES) { src = ei[e]; dst = ei[N_EDGES + e]; }
    else             { src = dst = e - N_EDGES; }
    int pos = atomicAdd(&g_cur[dst], 1);
    g_csr[pos] = src;
}

// ================= GEMM 1: h1 = x @ W1, per-head alpha dots =================
#define FMA4(acc, xv, wv) \
    acc.x = fmaf((xv), (wv).x, acc.x); acc.y = fmaf((xv), (wv).y, acc.y); \
    acc.z = fmaf((xv), (wv).z, acc.z); acc.w = fmaf((xv), (wv).w, acc.w);

__global__ __launch_bounds__(256) void k_gemm1(
        const float* __restrict__ x, const float* __restrict__ W1,
        const float* __restrict__ a_s, const float* __restrict__ a_d) {
    __shared__ float sW[64 * 64];
    __shared__ float sX[32 * 132];
    __shared__ float sas[64], sad[64];
    __shared__ float sAS[32 * 8], sAD[32 * 8];
    int t = threadIdx.x;
    int node0 = blockIdx.x * 32;
    if (t < 64) { sas[t] = a_s[t]; sad[t] = a_d[t]; }
    sAS[t] = 0.f; sAD[t] = 0.f;
#pragma unroll
    for (int i = 0; i < 16; i++) {
        int idx = t + 256 * i;
        int n = idx >> 7, k = idx & 127;
        sX[n * 132 + k] = x[(long long)(node0 + n) * F_IN + k];
    }
    int ng = t >> 4, cg = t & 15;
    int nA = ng * 2, nB = nA + 1;
    int c0 = cg * 4;
    float4 a0 = make_float4(0.f, 0.f, 0.f, 0.f);
    float4 a1 = make_float4(0.f, 0.f, 0.f, 0.f);

    for (int kc = 0; kc < 128; kc += 64) {
        __syncthreads();
#pragma unroll
        for (int i = 0; i < 16; i++) {
            int idx = t + 256 * i;
            int k = idx >> 6, c = idx & 63;
            sW[idx] = W1[(kc + k) * 64 + c];
        }
        __syncthreads();
#pragma unroll
        for (int k4 = 0; k4 < 64; k4 += 4) {
            float4 xa = *(const float4*)&sX[nA * 132 + kc + k4];
            float4 xb = *(const float4*)&sX[nB * 132 + kc + k4];
            float4 w0 = *(const float4*)&sW[(k4 + 0) * 64 + c0];
            float4 w1 = *(const float4*)&sW[(k4 + 1) * 64 + c0];
            float4 w2 = *(const float4*)&sW[(k4 + 2) * 64 + c0];
            float4 w3 = *(const float4*)&sW[(k4 + 3) * 64 + c0];
            FMA4(a0, xa.x, w0); FMA4(a0, xa.y, w1); FMA4(a0, xa.z, w2); FMA4(a0, xa.w, w3);
            FMA4(a1, xb.x, w0); FMA4(a1, xb.y, w1); FMA4(a1, xb.z, w2); FMA4(a1, xb.w, w3);
        }
    }
    int head = cg >> 1;
    *(float4*)&g_h1[(long long)(node0 + nA) * 64 + c0] = a0;
    *(float4*)&g_h1[(long long)(node0 + nB) * 64 + c0] = a1;
    float psA = a0.x * sas[c0] + a0.y * sas[c0 + 1] + a0.z * sas[c0 + 2] + a0.w * sas[c0 + 3];
    float pdA = a0.x * sad[c0] + a0.y * sad[c0 + 1] + a0.z * sad[c0 + 2] + a0.w * sad[c0 + 3];
    float psB = a1.x * sas[c0] + a1.y * sas[c0 + 1] + a1.z * sas[c0 + 2] + a1.w * sas[c0 + 3];
    float pdB = a1.x * sad[c0] + a1.y * sad[c0 + 1] + a1.z * sad[c0 + 2] + a1.w * sad[c0 + 3];
    atomicAdd(&sAS[nA * 8 + head], psA); atomicAdd(&sAD[nA * 8 + head], pdA);
    atomicAdd(&sAS[nB * 8 + head], psB); atomicAdd(&sAD[nB * 8 + head], pdB);
    __syncthreads();
    g_as1[node0 * 8 + t] = sAS[t];
    g_ad1[node0 * 8 + t] = sAD[t];
}

// ================= agg layer 1: warp/node, 2 edges per iter, float4/lane =================
__global__ __launch_bounds__(256) void k_agg1(const float* __restrict__ b1) {
    int warp = threadIdx.x >> 5, lane = threadIdx.x & 31;
    int node = blockIdx.x * 8 + warp;
    int sub  = lane >> 4;                  // which edge of the pair
    int l4   = lane & 15;                  // channel group within half-warp
    int c0   = l4 * 4;
    int head = l4 >> 1;                    // 8 channels / head, 4 per lane
    float adv = g_ad1[node * 8 + head];
    int beg = g_off[node], end = g_off[node + 1];
    int deg = end - beg;
    float4 acc = make_float4(0.f, 0.f, 0.f, 0.f);
    float den = 0.f;
    for (int base = 0; base < deg; base += 32) {
        int idx = base + lane;
        int sreg = (idx < deg) ? g_csr[beg + idx] : 0;
        int cnt = min(32, deg - base);
#pragma unroll 4
        for (int i = 0; i < cnt; i += 2) {
            int pair = i + sub;
            int s = __shfl_sync(FULLMASK, sreg, pair & 31);
            if (pair < cnt) {
                float asv = __ldg(&g_as1[s * 8 + head]);
                float ev = asv + adv;
                ev = ev > 0.f ? ev : 0.2f * ev;
                float p = __expf(ev);
                float4 h = *(const float4*)&g_h1[(long long)s * 64 + c0];
                acc.x = fmaf(p, h.x, acc.x); acc.y = fmaf(p, h.y, acc.y);
                acc.z = fmaf(p, h.z, acc.z); acc.w = fmaf(p, h.w, acc.w);
                den += p;
            }
        }
    }
    // merge the two half-warp edge streams
    acc.x += __shfl_xor_sync(FULLMASK, acc.x, 16);
    acc.y += __shfl_xor_sync(FULLMASK, acc.y, 16);
    acc.z += __shfl_xor_sync(FULLMASK, acc.z, 16);
    acc.w += __shfl_xor_sync(FULLMASK, acc.w, 16);
    den   += __shfl_xor_sync(FULLMASK, den, 16);
    float inv = 1.f / (den + 1e-16f);
    float4 bb = *(const float4*)&b1[c0];
    float4 v;
    v.x = acc.x * inv + bb.x; v.y = acc.y * inv + bb.y;
    v.z = acc.z * inv + bb.z; v.w = acc.w * inv + bb.w;
    v.x = v.x > 0.f ? v.x : expm1f(v.x);
    v.y = v.y > 0.f ? v.y : expm1f(v.y);
    v.z = v.z > 0.f ? v.z : expm1f(v.z);
    v.w = v.w > 0.f ? v.w : expm1f(v.w);
    if (sub == 0)
        *(float4*)&g_out1[(long long)node * 64 + c0] = v;
}

// ================= GEMM 2: h2 = out1 @ W2, alpha2 dots =================
__global__ __launch_bounds__(256) void k_gemm2(
        const float* __restrict__ W2,
        const float* __restrict__ a_s, const float* __restrict__ a_d) {
    __shared__ float sW[64 * 64];
    __shared__ float sX[32 * 68];
    __shared__ float sas[64], sad[64];
    __shared__ float sAS[32], sAD[32];
    int t = threadIdx.x;
    int node0 = blockIdx.x * 32;
    if (t < 64) { sas[t] = a_s[t]; sad[t] = a_d[t]; }
    if (t < 32) { sAS[t] = 0.f; sAD[t] = 0.f; }
#pragma unroll
    for (int i = 0; i < 8; i++) {
        int idx = t + 256 * i;
        int n = idx >> 6, k = idx & 63;
        sX[n * 68 + k] = g_out1[(long long)(node0 + n) * 64 + k];
    }
#pragma unroll
    for (int i = 0; i < 16; i++) {
        int idx = t + 256 * i;
        sW[idx] = W2[idx];
    }
    __syncthreads();
    int ng = t >> 4, cg = t & 15;
    int nA = ng * 2, nB = nA + 1;
    int c0 = cg * 4;
    float4 a0 = make_float4(0.f, 0.f, 0.f, 0.f);
    float4 a1 = make_float4(0.f, 0.f, 0.f, 0.f);
#pragma unroll
    for (int k4 = 0; k4 < 64; k4 += 4) {
        float4 xa = *(const float4*)&sX[nA * 68 + k4];
        float4 xb = *(const float4*)&sX[nB * 68 + k4];
        float4 w0 = *(const float4*)&sW[(k4 + 0) * 64 + c0];
        float4 w1 = *(const float4*)&sW[(k4 + 1) * 64 + c0];
        float4 w2 = *(const float4*)&sW[(k4 + 2) * 64 + c0];
        float4 w3 = *(const float4*)&sW[(k4 + 3) * 64 + c0];
        FMA4(a0, xa.x, w0); FMA4(a0, xa.y, w1); FMA4(a0, xa.z, w2); FMA4(a0, xa.w, w3);
        FMA4(a1, xb.x, w0); FMA4(a1, xb.y, w1); FMA4(a1, xb.z, w2); FMA4(a1, xb.w, w3);
    }
    *(float4*)&g_h2[(long long)(node0 + nA) * 64 + c0] = a0;
    *(float4*)&g_h2[(long long)(node0 + nB) * 64 + c0] = a1;
    float psA = a0.x * sas[c0] + a0.y * sas[c0 + 1] + a0.z * sas[c0 + 2] + a0.w * sas[c0 + 3];
    float pdA = a0.x * sad[c0] + a0.y * sad[c0 + 1] + a0.z * sad[c0 + 2] + a0.w * sad[c0 + 3];
    float psB = a1.x * sas[c0] + a1.y * sas[c0 + 1] + a1.z * sas[c0 + 2] + a1.w * sas[c0 + 3];
    float pdB = a1.x * sad[c0] + a1.y * sad[c0 + 1] + a1.z * sad[c0 + 2] + a1.w * sad[c0 + 3];
    atomicAdd(&sAS[nA], psA); atomicAdd(&sAD[nA], pdA);
    atomicAdd(&sAS[nB], psB); atomicAdd(&sAD[nB], pdB);
    __syncthreads();
    if (t < 32) { g_as2[node0 + t] = sAS[t]; g_ad2[node0 + t] = sAD[t]; }
}

// ================= agg layer 2 + bias + log_softmax =================
__global__ __launch_bounds__(256) void k_agg2(const float* __restrict__ b2,
                                              float* __restrict__ out) {
    int warp = threadIdx.x >> 5, lane = threadIdx.x & 31;
    int node = blockIdx.x * 8 + warp;
    int sub  = lane >> 4;
    int l4   = lane & 15;
    int c0   = l4 * 4;
    float adv = g_ad2[node];
    int beg = g_off[node], end = g_off[node + 1];
    int deg = end - beg;
    float4 acc = make_float4(0.f, 0.f, 0.f, 0.f);
    float den = 0.f;
    for (int base = 0; base < deg; base += 32) {
        int idx = base + lane;
        int sreg = (idx < deg) ? g_csr[beg + idx] : 0;
        int cnt = min(32, deg - base);
#pragma unroll 4
        for (int i = 0; i < cnt; i += 2) {
            int pair = i + sub;
            int s = __shfl_sync(FULLMASK, sreg, pair & 31);
            if (pair < cnt) {
                float asv = __ldg(&g_as2[s]);
                float ev = asv + adv;
                ev = ev > 0.f ? ev : 0.2f * ev;
                float p = __expf(ev);
                float4 h = *(const float4*)&g_h2[(long long)s * 64 + c0];
                acc.x = fmaf(p, h.x, acc.x); acc.y = fmaf(p, h.y, acc.y);
                acc.z = fmaf(p, h.z, acc.z); acc.w = fmaf(p, h.w, acc.w);
                den += p;
            }
        }
    }
    acc.x += __shfl_xor_sync(FULLMASK, acc.x, 16);
    acc.y += __shfl_xor_sync(FULLMASK, acc.y, 16);
    acc.z += __shfl_xor_sync(FULLMASK, acc.z, 16);
    acc.w += __shfl_xor_sync(FULLMASK, acc.w, 16);
    den   += __shfl_xor_sync(FULLMASK, den, 16);
    float inv = 1.f / (den + 1e-16f);
    float4 bb = *(const float4*)&b2[c0];
    float4 y;
    y.x = acc.x * inv + bb.x; y.y = acc.y * inv + bb.y;
    y.z = acc.z * inv + bb.z; y.w = acc.w * inv + bb.w;
    // log_softmax over 64 channels (only the 16 lanes of half 0 matter, but all compute)
    float m = fmaxf(fmaxf(y.x, y.y), fmaxf(y.z, y.w));
#pragma unroll
    for (int off = 8; off > 0; off >>= 1)
        m = fmaxf(m, __shfl_xor_sync(FULLMASK, m, off));
    float es = __expf(y.x - m) + __expf(y.y - m) + __expf(y.z - m) + __expf(y.w - m);
#pragma unroll
    for (int off = 8; off > 0; off >>= 1)
        es += __shfl_xor_sync(FULLMASK, es, off);
    float ls = m + __logf(es);
    if (sub == 0) {
        float4 r;
        r.x = y.x - ls; r.y = y.y - ls; r.z = y.z - ls; r.w = y.w - ls;
        *(float4*)&out[(long long)node * 64 + c0] = r;
    }
}

// ---------------- launcher ----------------
extern "C" void kernel_launch(void* const* d_in, const int* in_sizes, int n_in,
                              void* d_out, int out_size) {
    const float* x   = (const float*)d_in[0];
    const int*   ei  = (const int*)  d_in[1];
    const float* W1  = (const float*)d_in[2];
    const float* as1 = (const float*)d_in[3];
    const float* ad1 = (const float*)d_in[4];
    const float* b1  = (const float*)d_in[5];
    const float* W2  = (const float*)d_in[6];
    const float* as2 = (const float*)d_in[7];
    const float* ad2 = (const float*)d_in[8];
    const float* b2  = (const float*)d_in[9];
    float* out = (float*)d_out;

    int eblocks = (ET + 255) / 256;

    k_zero_deg<<<(N_NODES + 255) / 256, 256>>>();
    k_hist<<<eblocks, 256>>>(ei);
    k_sums<<<NTILES, SCAN_TILE>>>();
    k_top<<<1, 256>>>();
    k_fin<<<NTILES, SCAN_TILE>>>();
    k_scatter<<<eblocks, 256>>>(ei);

    k_gemm1<<<N_NODES / 32, 256>>>(x, W1, as1, ad1);
    k_agg1<<<N_NODES / 8, 256>>>(b1);
    k_gemm2<<<N_NODES / 32, 256>>>(W2, as2, ad2);
    k_agg2<<<N_NODES / 8, 256>>>(b2, out);
}